// round 3
// baseline (speedup 1.0000x reference)
#include <cuda_runtime.h>
#include <cuda_bf16.h>

#define GS_FX 500.0f

__device__ __forceinline__ float clipf(float v, float lo, float hi) {
    return fminf(fmaxf(v, lo), hi);
}

// ---------------------------------------------------------------------------
// Fused kernel, 4 gaussians/thread, phased to keep live registers low so the
// (256,8) launch bound (<=32 regs, 100% occupancy) is reachable.
//   phase 1: pos+scales -> proj, cov2d, valid
//   phase 2: colors+opacity -> clipped colors, sigmoid opacity
// ---------------------------------------------------------------------------
__global__ void __launch_bounds__(256, 8)
gs_fused_kernel(const float4* __restrict__ pos4,
                const float4* __restrict__ sc4,
                const float4* __restrict__ col4,
                const float4* __restrict__ op4,
                const float*  __restrict__ vm,
                const int*    __restrict__ wp,
                const int*    __restrict__ hp,
                float4* __restrict__ out4, int G)
{
    int g = blockIdx.x * blockDim.x + threadIdx.x;
    if (g >= G) return;

    // ---------------- phase 1: geometry ----------------
    {
        float4 p0 = pos4[3 * g], p1 = pos4[3 * g + 1], p2 = pos4[3 * g + 2];
        float4 s0 = sc4[3 * g],  s1 = sc4[3 * g + 1],  s2 = sc4[3 * g + 2];

        float W = (float)(*wp), H = (float)(*hp);
        float hw = W * 0.5f, hh = H * 0.5f;
        float xmax = W + 1000.0f, ymax = H + 1000.0f;

        float px[4] = {p0.x, p0.w, p1.z, p2.y};
        float py[4] = {p0.y, p1.x, p1.w, p2.z};
        float pz[4] = {p0.z, p1.y, p2.x, p2.w};
        float sx[4] = {s0.x, s0.w, s1.z, s2.y};
        float sy[4] = {s0.y, s1.x, s1.w, s2.z};

        float xs[4], ys[4], zs[4], c00[4], c11[4], vf[4];
#pragma unroll
        for (int j = 0; j < 4; j++) {
            float ax = px[j] - vm[3], ay = py[j] - vm[7], az = pz[j] - vm[11];
            float vx = clipf(fmaf(vm[0], ax, fmaf(vm[1], ay, vm[2]  * az)), -100.0f, 100.0f);
            float vy = clipf(fmaf(vm[4], ax, fmaf(vm[5], ay, vm[6]  * az)), -100.0f, 100.0f);
            float vz = clipf(fmaf(vm[8], ax, fmaf(vm[9], ay, vm[10] * az)), -100.0f, 100.0f);

            vf[j] = (vz > 0.1f && vz < 10.0f) ? 1.0f : 0.0f;

            float z   = clipf(vz, 0.1f, 10.0f);
            float inv = __fdividef(GS_FX, z);   // FX == FY

            xs[j] = clipf(fmaf(vx, inv, hw), -1000.0f, xmax);
            ys[j] = clipf(fmaf(-vy, inv, hh), -1000.0f, ymax);
            zs[j] = vz;

            float ssx = fmaxf(sx[j], 0.001f) * inv;
            float ssy = fmaxf(sy[j], 0.001f) * inv;
            c00[j] = clipf(fmaf(ssx, ssx, 1e-4f), 1e-6f, 1e6f);
            c11[j] = clipf(fmaf(ssy, ssy, 1e-4f), 1e-6f, 1e6f);
        }

        // proj_points: float4 [0, 3G)
        out4[3 * g + 0] = make_float4(xs[0], ys[0], zs[0], xs[1]);
        out4[3 * g + 1] = make_float4(ys[1], zs[1], xs[2], ys[2]);
        out4[3 * g + 2] = make_float4(zs[2], xs[3], ys[3], zs[3]);

        // cov2d: float4 [3G, 7G)
        long cb = 3L * G;
#pragma unroll
        for (int j = 0; j < 4; j++)
            out4[cb + 4L * g + j] = make_float4(c00[j], 1e-6f, 1e-6f, c11[j]);

        // valid: float4 [11G, 12G)
        out4[11L * G + g] = make_float4(vf[0], vf[1], vf[2], vf[3]);
    }

    // ---------------- phase 2: colors + opacity ----------------
    {
        float4 c0 = col4[3 * g], c1 = col4[3 * g + 1], c2 = col4[3 * g + 2];
        float4 o4 = op4[g];

        long kb = 7L * G;
        out4[kb + 3 * g + 0] = make_float4(clipf(c0.x,0.f,1.f), clipf(c0.y,0.f,1.f),
                                           clipf(c0.z,0.f,1.f), clipf(c0.w,0.f,1.f));
        out4[kb + 3 * g + 1] = make_float4(clipf(c1.x,0.f,1.f), clipf(c1.y,0.f,1.f),
                                           clipf(c1.z,0.f,1.f), clipf(c1.w,0.f,1.f));
        out4[kb + 3 * g + 2] = make_float4(clipf(c2.x,0.f,1.f), clipf(c2.y,0.f,1.f),
                                           clipf(c2.z,0.f,1.f), clipf(c2.w,0.f,1.f));

        o4.x = __fdividef(1.0f, 1.0f + __expf(-o4.x));
        o4.y = __fdividef(1.0f, 1.0f + __expf(-o4.y));
        o4.z = __fdividef(1.0f, 1.0f + __expf(-o4.z));
        o4.w = __fdividef(1.0f, 1.0f + __expf(-o4.w));
        out4[10L * G + g] = o4;
    }
}

// ---------------------------------------------------------------------------
// Scalar fallback for N % 4 != 0 (not expected with N = 4,000,000).
// ---------------------------------------------------------------------------
__global__ void __launch_bounds__(256)
gs_scalar_kernel(const float* __restrict__ pos,
                 const float* __restrict__ sc,
                 const float* __restrict__ col,
                 const float* __restrict__ op,
                 const float* __restrict__ vm,
                 const int*   __restrict__ wp,
                 const int*   __restrict__ hp,
                 float* __restrict__ out, int N)
{
    int i = blockIdx.x * blockDim.x + threadIdx.x;
    if (i >= N) return;

    float W = (float)(*wp), H = (float)(*hp);
    float hw = W * 0.5f, hh = H * 0.5f;
    float xmax = W + 1000.0f, ymax = H + 1000.0f;

    float ax = pos[3*i] - vm[3], ay = pos[3*i+1] - vm[7], az = pos[3*i+2] - vm[11];
    float vx = clipf(fmaf(vm[0], ax, fmaf(vm[1], ay, vm[2]  * az)), -100.0f, 100.0f);
    float vy = clipf(fmaf(vm[4], ax, fmaf(vm[5], ay, vm[6]  * az)), -100.0f, 100.0f);
    float vz = clipf(fmaf(vm[8], ax, fmaf(vm[9], ay, vm[10] * az)), -100.0f, 100.0f);

    float z   = clipf(vz, 0.1f, 10.0f);
    float inv = __fdividef(GS_FX, z);

    long n = N;
    out[3*i+0] = clipf(fmaf(vx, inv, hw), -1000.0f, xmax);
    out[3*i+1] = clipf(fmaf(-vy, inv, hh), -1000.0f, ymax);
    out[3*i+2] = vz;

    float ssx = fmaxf(sc[3*i],   0.001f) * inv;
    float ssy = fmaxf(sc[3*i+1], 0.001f) * inv;
    out[3*n + 4L*i + 0] = clipf(fmaf(ssx, ssx, 1e-4f), 1e-6f, 1e6f);
    out[3*n + 4L*i + 1] = 1e-6f;
    out[3*n + 4L*i + 2] = 1e-6f;
    out[3*n + 4L*i + 3] = clipf(fmaf(ssy, ssy, 1e-4f), 1e-6f, 1e6f);

    out[7*n + 3L*i + 0] = clipf(col[3*i+0], 0.f, 1.f);
    out[7*n + 3L*i + 1] = clipf(col[3*i+1], 0.f, 1.f);
    out[7*n + 3L*i + 2] = clipf(col[3*i+2], 0.f, 1.f);

    out[10*n + i] = __fdividef(1.0f, 1.0f + __expf(-op[i]));
    out[11*n + i] = (vz > 0.1f && vz < 10.0f) ? 1.0f : 0.0f;
}

extern "C" void kernel_launch(void* const* d_in, const int* in_sizes, int n_in,
                              void* d_out, int out_size)
{
    const float* positions = (const float*)d_in[0];
    const float* scales    = (const float*)d_in[1];
    // d_in[2] rotations: unused by the reference math
    const float* colors    = (const float*)d_in[3];
    const float* opac      = (const float*)d_in[4];
    const float* viewmat   = (const float*)d_in[5];
    // d_in[6] projmat: unused
    const int*   wp        = (const int*)d_in[7];
    const int*   hp        = (const int*)d_in[8];
    float* out = (float*)d_out;

    int N = in_sizes[0] / 3;

    if ((N & 3) == 0) {
        int G = N >> 2;
        int threads = 256;
        int blocks = (G + threads - 1) / threads;
        gs_fused_kernel<<<blocks, threads>>>(
            (const float4*)positions, (const float4*)scales,
            (const float4*)colors, (const float4*)opac,
            viewmat, wp, hp, (float4*)out, G);
    } else {
        int threads = 256;
        int blocks = (N + threads - 1) / threads;
        gs_scalar_kernel<<<blocks, threads>>>(
            positions, scales, colors, opac, viewmat, wp, hp, out, N);
    }
}

// round 4
// speedup vs baseline: 1.0937x; 1.0937x over previous
#include <cuda_runtime.h>
#include <cuda_bf16.h>

#define GS_FX 500.0f

__device__ __forceinline__ float clipf(float v, float lo, float hi) {
    return fminf(fmaxf(v, lo), hi);
}

// ---------------------------------------------------------------------------
// Fused kernel, 4 gaussians/thread, all global traffic coalesced.
//  - pos/scales staged in via smem (unit-stride global loads)
//  - proj staged out via smem (unit-stride global stores)
//  - colors handled flat/elementwise (naturally coalesced)
//  - opacity & valid: one float4 per thread (coalesced)
//  - cov2d: direct stores, 64B lane stride (lines fully covered by 4-unroll)
// ---------------------------------------------------------------------------
__global__ void __launch_bounds__(256)
gs_fused_kernel(const float4* __restrict__ pos4,
                const float4* __restrict__ sc4,
                const float4* __restrict__ col4,
                const float4* __restrict__ op4,
                const float*  __restrict__ vm,
                const int*    __restrict__ wp,
                const int*    __restrict__ hp,
                float4* __restrict__ out4, int G)
{
    __shared__ float4 s_a[768];   // pos in, then proj out
    __shared__ float4 s_b[768];   // scales in

    int  t    = threadIdx.x;
    long base = (long)blockIdx.x * 256;       // first gaussian-group of block
    long fb   = 3 * base;                     // first float4 of block's slice
    long G3   = 3L * G;

    // coalesced staging of pos + scales
#pragma unroll
    for (int k = 0; k < 3; k++) {
        long idx = fb + t + k * 256;
        if (idx < G3) {
            s_a[t + k * 256] = pos4[idx];
            s_b[t + k * 256] = sc4[idx];
        }
    }
    __syncthreads();

    bool active = (base + t) < G;
    long g = base + t;

    float4 p0, p1, p2, s0, s1, s2;
    if (active) {
        p0 = s_a[3 * t]; p1 = s_a[3 * t + 1]; p2 = s_a[3 * t + 2];
        s0 = s_b[3 * t]; s1 = s_b[3 * t + 1]; s2 = s_b[3 * t + 2];
    }
    __syncthreads();   // everyone done reading s_a before proj overwrites it

    float W = (float)(*wp), H = (float)(*hp);
    float hw = W * 0.5f, hh = H * 0.5f;
    float xmax = W + 1000.0f, ymax = H + 1000.0f;

    float xs[4], ys[4], zs[4], c00[4], c11[4], vf[4];
    if (active) {
        float px[4] = {p0.x, p0.w, p1.z, p2.y};
        float py[4] = {p0.y, p1.x, p1.w, p2.z};
        float pz[4] = {p0.z, p1.y, p2.x, p2.w};
        float sx[4] = {s0.x, s0.w, s1.z, s2.y};
        float sy[4] = {s0.y, s1.x, s1.w, s2.z};

#pragma unroll
        for (int j = 0; j < 4; j++) {
            float ax = px[j] - vm[3], ay = py[j] - vm[7], az = pz[j] - vm[11];
            float vx = clipf(fmaf(vm[0], ax, fmaf(vm[1], ay, vm[2]  * az)), -100.0f, 100.0f);
            float vy = clipf(fmaf(vm[4], ax, fmaf(vm[5], ay, vm[6]  * az)), -100.0f, 100.0f);
            float vz = clipf(fmaf(vm[8], ax, fmaf(vm[9], ay, vm[10] * az)), -100.0f, 100.0f);

            vf[j] = (vz > 0.1f && vz < 10.0f) ? 1.0f : 0.0f;

            float z   = clipf(vz, 0.1f, 10.0f);
            float inv = __fdividef(GS_FX, z);   // FX == FY

            xs[j] = clipf(fmaf(vx, inv, hw), -1000.0f, xmax);
            ys[j] = clipf(fmaf(-vy, inv, hh), -1000.0f, ymax);
            zs[j] = vz;

            float ssx = fmaxf(sx[j], 0.001f) * inv;
            float ssy = fmaxf(sy[j], 0.001f) * inv;
            c00[j] = clipf(fmaf(ssx, ssx, 1e-4f), 1e-6f, 1e6f);
            c11[j] = clipf(fmaf(ssy, ssy, 1e-4f), 1e-6f, 1e6f);
        }

        // stage proj into smem
        s_a[3 * t + 0] = make_float4(xs[0], ys[0], zs[0], xs[1]);
        s_a[3 * t + 1] = make_float4(ys[1], zs[1], xs[2], ys[2]);
        s_a[3 * t + 2] = make_float4(zs[2], xs[3], ys[3], zs[3]);
    }
    __syncthreads();

    // coalesced proj store: float4 [0, 3G)
#pragma unroll
    for (int k = 0; k < 3; k++) {
        long idx = fb + t + k * 256;
        if (idx < G3) out4[idx] = s_a[t + k * 256];
    }

    if (active) {
        // cov2d: float4 [3G, 7G) — direct, 64B lane stride
        long cb = 3L * G;
#pragma unroll
        for (int j = 0; j < 4; j++)
            out4[cb + 4L * g + j] = make_float4(c00[j], 1e-6f, 1e-6f, c11[j]);

        // valid: float4 [11G, 12G) — coalesced
        out4[11L * G + g] = make_float4(vf[0], vf[1], vf[2], vf[3]);
    }

    // colors: pure elementwise, flat & coalesced: float4 [7G, 10G)
#pragma unroll
    for (int k = 0; k < 3; k++) {
        long idx = fb + t + k * 256;
        if (idx < G3) {
            float4 c = col4[idx];
            c.x = clipf(c.x, 0.0f, 1.0f);
            c.y = clipf(c.y, 0.0f, 1.0f);
            c.z = clipf(c.z, 0.0f, 1.0f);
            c.w = clipf(c.w, 0.0f, 1.0f);
            out4[7L * G + idx] = c;
        }
    }

    // opacity: float4 [10G, 11G) — coalesced
    if (active) {
        float4 o = op4[g];
        o.x = __fdividef(1.0f, 1.0f + __expf(-o.x));
        o.y = __fdividef(1.0f, 1.0f + __expf(-o.y));
        o.z = __fdividef(1.0f, 1.0f + __expf(-o.z));
        o.w = __fdividef(1.0f, 1.0f + __expf(-o.w));
        out4[10L * G + g] = o;
    }
}

// ---------------------------------------------------------------------------
// Scalar fallback for N % 4 != 0 (not expected with N = 4,000,000).
// ---------------------------------------------------------------------------
__global__ void __launch_bounds__(256)
gs_scalar_kernel(const float* __restrict__ pos,
                 const float* __restrict__ sc,
                 const float* __restrict__ col,
                 const float* __restrict__ op,
                 const float* __restrict__ vm,
                 const int*   __restrict__ wp,
                 const int*   __restrict__ hp,
                 float* __restrict__ out, int N)
{
    int i = blockIdx.x * blockDim.x + threadIdx.x;
    if (i >= N) return;

    float W = (float)(*wp), H = (float)(*hp);
    float hw = W * 0.5f, hh = H * 0.5f;
    float xmax = W + 1000.0f, ymax = H + 1000.0f;

    float ax = pos[3*i] - vm[3], ay = pos[3*i+1] - vm[7], az = pos[3*i+2] - vm[11];
    float vx = clipf(fmaf(vm[0], ax, fmaf(vm[1], ay, vm[2]  * az)), -100.0f, 100.0f);
    float vy = clipf(fmaf(vm[4], ax, fmaf(vm[5], ay, vm[6]  * az)), -100.0f, 100.0f);
    float vz = clipf(fmaf(vm[8], ax, fmaf(vm[9], ay, vm[10] * az)), -100.0f, 100.0f);

    float z   = clipf(vz, 0.1f, 10.0f);
    float inv = __fdividef(GS_FX, z);

    long n = N;
    out[3*i+0] = clipf(fmaf(vx, inv, hw), -1000.0f, xmax);
    out[3*i+1] = clipf(fmaf(-vy, inv, hh), -1000.0f, ymax);
    out[3*i+2] = vz;

    float ssx = fmaxf(sc[3*i],   0.001f) * inv;
    float ssy = fmaxf(sc[3*i+1], 0.001f) * inv;
    out[3*n + 4L*i + 0] = clipf(fmaf(ssx, ssx, 1e-4f), 1e-6f, 1e6f);
    out[3*n + 4L*i + 1] = 1e-6f;
    out[3*n + 4L*i + 2] = 1e-6f;
    out[3*n + 4L*i + 3] = clipf(fmaf(ssy, ssy, 1e-4f), 1e-6f, 1e6f);

    out[7*n + 3L*i + 0] = clipf(col[3*i+0], 0.f, 1.f);
    out[7*n + 3L*i + 1] = clipf(col[3*i+1], 0.f, 1.f);
    out[7*n + 3L*i + 2] = clipf(col[3*i+2], 0.f, 1.f);

    out[10*n + i] = __fdividef(1.0f, 1.0f + __expf(-op[i]));
    out[11*n + i] = (vz > 0.1f && vz < 10.0f) ? 1.0f : 0.0f;
}

extern "C" void kernel_launch(void* const* d_in, const int* in_sizes, int n_in,
                              void* d_out, int out_size)
{
    const float* positions = (const float*)d_in[0];
    const float* scales    = (const float*)d_in[1];
    // d_in[2] rotations: unused by the reference math
    const float* colors    = (const float*)d_in[3];
    const float* opac      = (const float*)d_in[4];
    const float* viewmat   = (const float*)d_in[5];
    // d_in[6] projmat: unused
    const int*   wp        = (const int*)d_in[7];
    const int*   hp        = (const int*)d_in[8];
    float* out = (float*)d_out;

    int N = in_sizes[0] / 3;

    if ((N & 3) == 0) {
        int G = N >> 2;
        int threads = 256;
        int blocks = (G + threads - 1) / threads;
        gs_fused_kernel<<<blocks, threads>>>(
            (const float4*)positions, (const float4*)scales,
            (const float4*)colors, (const float4*)opac,
            viewmat, wp, hp, (float4*)out, G);
    } else {
        int threads = 256;
        int blocks = (N + threads - 1) / threads;
        gs_scalar_kernel<<<blocks, threads>>>(
            positions, scales, colors, opac, viewmat, wp, hp, out, N);
    }
}